// round 1
// baseline (speedup 1.0000x reference)
#include <cuda_runtime.h>

typedef unsigned long long u64;
#define FULLMASK 0xffffffffu

__device__ __forceinline__ void ffma2(u64 &d, u64 a, u64 b) {
    asm("fma.rn.f32x2 %0, %1, %2, %0;" : "+l"(d) : "l"(a), "l"(b));
}
__device__ __forceinline__ u64 fadd2(u64 a, u64 b) {
    u64 d; asm("add.rn.f32x2 %0, %1, %2;" : "=l"(d) : "l"(a), "l"(b));
    return d;
}
__device__ __forceinline__ u64 pack2(float x) {
    u64 r; asm("mov.b64 %0, {%1, %1};" : "=l"(r) : "f"(x));
    return r;
}

__device__ float g_losses[256];

// CTA-wide max over 128 threads (4 warps). Caller guarantees sred is safe to
// write (a barrier separates any previous read of sred from this call).
__device__ __forceinline__ float ctamax128(float v, volatile float* sred, int tid) {
    #pragma unroll
    for (int o = 16; o; o >>= 1) v = fmaxf(v, __shfl_xor_sync(FULLMASK, v, o));
    if ((tid & 31) == 0) sred[tid >> 5] = v;
    __syncthreads();
    v = fmaxf(fmaxf(sred[0], sred[1]), fmaxf(sred[2], sred[3]));
    __syncthreads();  // protect sred for reuse
    return v;
}

__device__ __forceinline__ float ctasum128(float v, volatile float* sred, int tid) {
    #pragma unroll
    for (int o = 16; o; o >>= 1) v += __shfl_xor_sync(FULLMASK, v, o);
    if ((tid & 31) == 0) sred[tid >> 5] = v;
    __syncthreads();
    v = sred[0] + sred[1] + sred[2] + sred[3];
    __syncthreads();
    return v;
}

// One CTA per batch element. 128 threads.
// Forward algorithm in exp-domain with deferred rescaling every 8 steps.
__global__ void __launch_bounds__(128, 1) k_crf_forward(
    const float* __restrict__ feats,   // [B,S,L]
    const float* __restrict__ startT,  // [L]
    const float* __restrict__ endT,    // [L]
    const float* __restrict__ trans,   // [L,L]
    const float* __restrict__ conf,    // [B]
    const int*   __restrict__ mask,    // [B,S]
    const int*   __restrict__ labels,  // [B,S]
    int S)
{
    constexpr int L = 128;
    extern __shared__ char smemraw[];
    float* sT    = (float*)smemraw;                                   // L*L = 64KB, exp(T)
    u64*   se2   = (u64*)  (smemraw + L*L*4);                         // L duplicated-pair e vec
    float* spart = (float*)(smemraw + L*L*4 + L*8);                   // 2*L partials
    int*   smask = (int*)  (smemraw + L*L*4 + L*8 + 2*L*4);           // S
    float* sred  = (float*)(smemraw + L*L*4 + L*8 + 2*L*4 + S*4);     // 4

    const int tid = threadIdx.x;
    const int b   = blockIdx.x;
    const int ih  = tid >> 6;   // i-half: 0 -> i in [0,64), 1 -> [64,128)
    const int jj  = tid & 63;   // column pair: cols (2jj, 2jj+1)
    const int c   = tid;        // epilogue: this thread owns column c

    const float* fb = feats + (size_t)b * S * L;

    // Precompute exp(transitions) into shared.
    #pragma unroll 4
    for (int k = tid; k < L * L; k += 128) sT[k] = __expf(trans[k]);
    for (int k = tid; k < S; k += 128) smask[k] = mask[b * S + k];

    // alpha0 = start + feats[:,0,:]
    float a0 = startT[c] + fb[c];
    __syncthreads();                       // sT/smask ready; sred safe
    float m0 = ctamax128(a0, sred, tid);
    float v = __expf(a0 - m0);             // exp-domain alpha, max-normalized
    float offset = m0;                     // alpha_c = offset + log(v_c)
    se2[c] = pack2(v);

    float fA = (S > 1) ? fb[1 * L + c] : 0.f;   // prefetch feat(t=1)
    float fB = (S > 2) ? fb[2 * L + c] : 0.f;   // prefetch feat(t=2)
    __syncthreads();

    const u64* sT2 = (const u64*)sT;                 // float2 view of expT rows
    const ulonglong2* se4 = (const ulonglong2*)se2;  // 2 duplicated pairs / load
    const int rowbase = ih * 64 * 64 + jj;           // (i = ih*64)*64 + jj
    const int ebase   = ih * 32;

    for (int t = 1; t < S; ++t) {
        // Partial dot over this thread's i-half for its 2 columns (f32x2).
        u64 acc0 = 0ULL, acc1 = 0ULL;
        #pragma unroll
        for (int p = 0; p < 32; ++p) {
            ulonglong2 ee = se4[ebase + p];            // (e_i,e_i),(e_{i+1},e_{i+1})
            u64 t0 = sT2[rowbase + p * 128];           // expT[i][2jj..2jj+1]
            u64 t1 = sT2[rowbase + p * 128 + 64];      // expT[i+1][..]
            ffma2(acc0, ee.x, t0);
            ffma2(acc1, ee.y, t1);
        }
        *(u64*)(spart + 2 * tid) = fadd2(acc0, acc1);

        float fcur = fA;
        fA = fB;
        if (t + 2 < S) fB = fb[(size_t)(t + 2) * L + c];   // prefetch
        __syncthreads();

        // Combine i-halves for column c, fold emission.
        float s = spart[c] + spart[128 + c];
        if (smask[t]) v = s * __expf(fcur);
        // else: masked step, alpha (and v) carries over unchanged.

        if ((t & 7) == 0) {   // deferred rescale: keep exp-domain in fp32 range
            float mm = ctamax128(v, sred, tid);
            v *= (1.0f / mm);
            offset += __logf(mm);
        }
        se2[c] = pack2(v);
        __syncthreads();
    }

    // Denominator: log_den = offset + log(sum_j v_j * exp(end_j))
    float contrib = v * __expf(endT[c]);
    float ssum = ctasum128(contrib, sred, tid);
    float log_den = offset + __logf(ssum);

    // Numerator: score of the label path.
    float num = 0.f;
    float slf = 0.f;
    const int* lb = labels + b * S;
    for (int k = c; k < S; k += 128) {
        int mk = smask[k];
        slf += (float)mk;
        int lab = lb[k]; if (lab == -100) lab = 0;
        if (k == 0) {
            num += startT[lab] + fb[lab];
        } else if (mk) {
            int lp = lb[k - 1]; if (lp == -100) lp = 0;
            num += trans[lp * L + lab] + fb[(size_t)k * L + lab];
        }
    }
    num = ctasum128(num, sred, tid);
    slf = ctasum128(slf, sred, tid);
    int lastt = (int)(slf + 0.5f) - 1;
    if (lastt < 0) lastt = 0;
    int lastlab = lb[lastt]; if (lastlab == -100) lastlab = 0;
    num += endT[lastlab];

    if (tid == 0) g_losses[b] = (log_den - num) * conf[b];
}

__global__ void k_finalize(float* __restrict__ out, int B) {
    int t = threadIdx.x;
    float x = (t < B) ? g_losses[t] : 0.f;
    #pragma unroll
    for (int o = 16; o; o >>= 1) x += __shfl_xor_sync(FULLMASK, x, o);
    __shared__ float sh[8];
    if ((t & 31) == 0) sh[t >> 5] = x;
    __syncthreads();
    if (t == 0) {
        float s = 0.f;
        int nw = (blockDim.x + 31) >> 5;
        for (int w = 0; w < nw; ++w) s += sh[w];
        out[0] = s / (float)B;
    }
}

extern "C" void kernel_launch(void* const* d_in, const int* in_sizes, int n_in,
                              void* d_out, int out_size) {
    const float* feats  = (const float*)d_in[0];
    const float* startT = (const float*)d_in[1];
    const float* endT   = (const float*)d_in[2];
    const float* trans  = (const float*)d_in[3];
    const float* conf   = (const float*)d_in[4];
    const int*   mask   = (const int*)  d_in[5];
    const int*   labels = (const int*)  d_in[6];

    const int L = in_sizes[1];            // 128
    const int B = in_sizes[4];            // 256
    const int S = in_sizes[5] / B;        // 512
    (void)L; (void)n_in; (void)out_size;

    size_t smem = (size_t)128 * 128 * 4   // expT
                + 128 * 8                 // e2 duplicated pairs
                + 256 * 4                 // partials
                + (size_t)S * 4           // mask
                + 64;                     // reduction scratch

    cudaFuncSetAttribute(k_crf_forward,
                         cudaFuncAttributeMaxDynamicSharedMemorySize, (int)smem);

    k_crf_forward<<<B, 128, smem>>>(feats, startT, endT, trans, conf,
                                    mask, labels, S);
    k_finalize<<<1, 256>>>((float*)d_out, B);
}

// round 2
// speedup vs baseline: 2.1900x; 2.1900x over previous
#include <cuda_runtime.h>

typedef unsigned long long u64;
#define FULLMASK 0xffffffffu

__device__ __forceinline__ void ffma2(u64 &d, u64 a, u64 b) {
    asm("fma.rn.f32x2 %0, %1, %2, %0;" : "+l"(d) : "l"(a), "l"(b));
}
__device__ __forceinline__ u64 fadd2(u64 a, u64 b) {
    u64 d; asm("add.rn.f32x2 %0, %1, %2;" : "=l"(d) : "l"(a), "l"(b));
    return d;
}
__device__ __forceinline__ u64 pack2f(float x, float y) {
    u64 r; asm("mov.b64 %0, {%1, %2};" : "=l"(r) : "f"(x), "f"(y));
    return r;
}
__device__ __forceinline__ void unpack2(u64 v, float &lo, float &hi) {
    asm("mov.b64 {%0, %1}, %2;" : "=f"(lo), "=f"(hi) : "l"(v));
}

__device__ float g_losses[256];

// e-vector buffer layout: 4 sections (one per i-quarter), each 32 duplicated
// u64 pairs = 256B, padded +16B so the 4 sections start on distinct banks.
#define SEC_BYTES 272            // 256 + 16 pad
#define EBUF_BYTES (4 * SEC_BYTES)

__device__ __forceinline__ void store_e(char* buf, int c, float v) {
    // col c lives in section c>>5, entry (c&31)>>1, half c&1
    u64* p = (u64*)(buf + (c >> 5) * SEC_BYTES + ((c & 31) >> 1) * 16 + (c & 1) * 8);
    *p = pack2f(v, v);
}

__device__ __forceinline__ float ctamax128(float v, volatile float* sred, int tid) {
    #pragma unroll
    for (int o = 16; o; o >>= 1) v = fmaxf(v, __shfl_xor_sync(FULLMASK, v, o));
    if ((tid & 31) == 0) sred[tid >> 5] = v;
    __syncthreads();
    v = fmaxf(fmaxf(sred[0], sred[1]), fmaxf(sred[2], sred[3]));
    __syncthreads();
    return v;
}

__device__ __forceinline__ float ctasum128(float v, volatile float* sred, int tid) {
    #pragma unroll
    for (int o = 16; o; o >>= 1) v += __shfl_xor_sync(FULLMASK, v, o);
    if ((tid & 31) == 0) sred[tid >> 5] = v;
    __syncthreads();
    v = sred[0] + sred[1] + sred[2] + sred[3];
    __syncthreads();
    return v;
}

// One CTA per batch element. 128 threads, 2 CTAs/SM.
// exp-domain forward recurrence; expT entirely in registers.
__global__ void __launch_bounds__(128, 2) k_crf_forward(
    const float* __restrict__ feats,   // [B,S,L]
    const float* __restrict__ startT,  // [L]
    const float* __restrict__ endT,    // [L]
    const float* __restrict__ trans,   // [L,L]
    const float* __restrict__ conf,    // [B]
    const int*   __restrict__ mask,    // [B,S]
    const int*   __restrict__ labels,  // [B,S]
    int S)
{
    constexpr int L = 128;
    extern __shared__ char sm[];
    char*  ebuf0 = sm;
    char*  ebuf1 = sm + EBUF_BYTES;
    int*   smask = (int*)(sm + 2 * EBUF_BYTES);
    float* sred  = (float*)(sm + 2 * EBUF_BYTES + S * 4);

    const int tid = threadIdx.x;
    const int b   = blockIdx.x;
    const int jj  = tid >> 2;   // column group: cols 4jj..4jj+3
    const int iq  = tid & 3;    // i-quarter: i in [32iq, 32iq+32)
    const int c   = tid;        // owned column for e/v/feats (c == tid)

    const float* fb = feats + (size_t)b * S * L;

    // ---- load this thread's expT slice into registers: 32 i x 4 cols ----
    u64 TA[32], TB[32];
    {
        const float* tr = trans + (size_t)(32 * iq) * L + 4 * jj;
        #pragma unroll
        for (int p = 0; p < 32; ++p) {
            float t0 = __expf(__ldg(tr + (size_t)p * L + 0));
            float t1 = __expf(__ldg(tr + (size_t)p * L + 1));
            float t2 = __expf(__ldg(tr + (size_t)p * L + 2));
            float t3 = __expf(__ldg(tr + (size_t)p * L + 3));
            TA[p] = pack2f(t0, t1);
            TB[p] = pack2f(t2, t3);
        }
    }
    for (int k = tid; k < S; k += 128) smask[k] = mask[b * S + k];

    // ---- alpha0 ----
    float a0 = startT[c] + fb[c];
    __syncthreads();                       // smask ready; sred safe
    float m0 = ctamax128(a0, sred, tid);
    float v = __expf(a0 - m0);             // exp-domain alpha, normalized
    float offset = m0;
    store_e(ebuf1, c, v);                  // first read (t=1) uses ebuf1

    float fA = fb[L + c];                            // feat(t=1)
    float fB = (S > 2) ? fb[2 * (size_t)L + c] : 0.f; // feat(t=2)
    __syncthreads();

    char* rbuf = ebuf1;
    char* wbuf = ebuf0;

    for (int t = 1; t < S; ++t) {
        const ulonglong2* se = (const ulonglong2*)(rbuf + iq * SEC_BYTES);
        u64 accA = 0ULL, accB = 0ULL;
        #pragma unroll
        for (int p = 0; p < 16; ++p) {
            ulonglong2 ee = se[p];   // ((e_i,e_i),(e_{i+1},e_{i+1})), i=32iq+2p
            ffma2(accA, ee.x, TA[2 * p]);
            ffma2(accA, ee.y, TA[2 * p + 1]);
            ffma2(accB, ee.x, TB[2 * p]);
            ffma2(accB, ee.y, TB[2 * p + 1]);
        }
        // combine i-quarters (partners are lanes xor 1, xor 2)
        accA = fadd2(accA, __shfl_xor_sync(FULLMASK, accA, 1));
        accB = fadd2(accB, __shfl_xor_sync(FULLMASK, accB, 1));
        accA = fadd2(accA, __shfl_xor_sync(FULLMASK, accA, 2));
        accB = fadd2(accB, __shfl_xor_sync(FULLMASK, accB, 2));

        float fcur = fA;
        fA = fB;
        if (t + 2 < S) fB = fb[(size_t)(t + 2) * L + c];   // prefetch

        // select sum for this thread's own column c = 4jj+iq
        u64 sel = (iq & 2) ? accB : accA;
        float lo, hi; unpack2(sel, lo, hi);
        float s = (iq & 1) ? hi : lo;

        if (smask[t]) v = s * __expf(fcur);
        // else masked: v (alpha) carries over

        if ((t & 7) == 0) {   // deferred rescale keeps exp-domain in range
            float mm = ctamax128(v, sred, tid);
            v *= (1.0f / mm);
            offset += __logf(mm);
        }
        store_e(wbuf, c, v);
        { char* tmp = rbuf; rbuf = wbuf; wbuf = tmp; }
        __syncthreads();
    }

    // ---- denominator ----
    float contrib = v * __expf(endT[c]);
    float ssum = ctasum128(contrib, sred, tid);
    float log_den = offset + __logf(ssum);

    // ---- numerator: label-path score ----
    float num = 0.f;
    float slf = 0.f;
    const int* lb = labels + b * S;
    for (int k = c; k < S; k += 128) {
        int mk = smask[k];
        slf += (float)mk;
        int lab = lb[k]; if (lab == -100) lab = 0;
        if (k == 0) {
            num += startT[lab] + fb[lab];
        } else if (mk) {
            int lp = lb[k - 1]; if (lp == -100) lp = 0;
            num += trans[lp * L + lab] + fb[(size_t)k * L + lab];
        }
    }
    num = ctasum128(num, sred, tid);
    slf = ctasum128(slf, sred, tid);
    int lastt = (int)(slf + 0.5f) - 1;
    if (lastt < 0) lastt = 0;
    int lastlab = lb[lastt]; if (lastlab == -100) lastlab = 0;
    num += endT[lastlab];

    if (tid == 0) g_losses[b] = (log_den - num) * conf[b];
}

__global__ void k_finalize(float* __restrict__ out, int B) {
    int t = threadIdx.x;
    float x = (t < B) ? g_losses[t] : 0.f;
    #pragma unroll
    for (int o = 16; o; o >>= 1) x += __shfl_xor_sync(FULLMASK, x, o);
    __shared__ float sh[8];
    if ((t & 31) == 0) sh[t >> 5] = x;
    __syncthreads();
    if (t == 0) {
        float s = 0.f;
        int nw = (blockDim.x + 31) >> 5;
        for (int w = 0; w < nw; ++w) s += sh[w];
        out[0] = s / (float)B;
    }
}

extern "C" void kernel_launch(void* const* d_in, const int* in_sizes, int n_in,
                              void* d_out, int out_size) {
    const float* feats  = (const float*)d_in[0];
    const float* startT = (const float*)d_in[1];
    const float* endT   = (const float*)d_in[2];
    const float* trans  = (const float*)d_in[3];
    const float* conf   = (const float*)d_in[4];
    const int*   mask   = (const int*)  d_in[5];
    const int*   labels = (const int*)  d_in[6];

    const int B = in_sizes[4];            // 256
    const int S = in_sizes[5] / B;        // 512
    (void)n_in; (void)out_size;

    size_t smem = 2 * EBUF_BYTES          // double-buffered e vectors
                + (size_t)S * 4           // mask
                + 64;                     // reduction scratch

    k_crf_forward<<<B, 128, smem>>>(feats, startT, endT, trans, conf,
                                    mask, labels, S);
    k_finalize<<<1, 256>>>((float*)d_out, B);
}

// round 3
// speedup vs baseline: 2.1946x; 1.0021x over previous
#include <cuda_runtime.h>

typedef unsigned long long u64;
#define FULLMASK 0xffffffffu

__device__ __forceinline__ void ffma2(u64 &d, u64 a, u64 b) {
    asm("fma.rn.f32x2 %0, %1, %2, %0;" : "+l"(d) : "l"(a), "l"(b));
}
__device__ __forceinline__ u64 fadd2(u64 a, u64 b) {
    u64 d; asm("add.rn.f32x2 %0, %1, %2;" : "=l"(d) : "l"(a), "l"(b));
    return d;
}
__device__ __forceinline__ u64 pack2f(float x, float y) {
    u64 r; asm("mov.b64 %0, {%1, %2};" : "=l"(r) : "f"(x), "f"(y));
    return r;
}
__device__ __forceinline__ void unpack2(u64 v, float &lo, float &hi) {
    asm("mov.b64 {%0, %1}, %2;" : "=f"(lo), "=f"(hi) : "l"(v));
}

__device__ float g_losses[256];

// e-vector buffer: half0 = 64 floats @ byte 0, half1 = 64 floats @ byte 272.
// The 272-byte offset (256 + 16) shifts half1 by 4 banks so the paired
// even/odd-lane LDS.128 accesses hit distinct banks.
#define EHALF_BYTES 272
#define EBUF_BYTES  (2 * EHALF_BYTES)

// CTA-wide reductions over 256 threads (8 warps).
__device__ __forceinline__ float ctamax(float v, volatile float* sred, int tid) {
    #pragma unroll
    for (int o = 16; o; o >>= 1) v = fmaxf(v, __shfl_xor_sync(FULLMASK, v, o));
    if ((tid & 31) == 0) sred[tid >> 5] = v;
    __syncthreads();
    v = fmaxf(fmaxf(fmaxf(sred[0], sred[1]), fmaxf(sred[2], sred[3])),
              fmaxf(fmaxf(sred[4], sred[5]), fmaxf(sred[6], sred[7])));
    __syncthreads();
    return v;
}
__device__ __forceinline__ float ctasum(float v, volatile float* sred, int tid) {
    #pragma unroll
    for (int o = 16; o; o >>= 1) v += __shfl_xor_sync(FULLMASK, v, o);
    if ((tid & 31) == 0) sred[tid >> 5] = v;
    __syncthreads();
    v = (sred[0] + sred[1]) + (sred[2] + sred[3])
      + (sred[4] + sred[5]) + (sred[6] + sred[7]);
    __syncthreads();
    return v;
}

// One CTA per batch element. 256 threads, 2 CTAs/SM.
// thread = (column, i-half): col = tid>>1, ih = tid&1 (i in [64*ih, 64*ih+64)).
__global__ void __launch_bounds__(256, 2) k_crf_forward(
    const float* __restrict__ feats,   // [B,S,L]
    const float* __restrict__ startT,  // [L]
    const float* __restrict__ endT,    // [L]
    const float* __restrict__ trans,   // [L,L]
    const float* __restrict__ conf,    // [B]
    const int*   __restrict__ mask,    // [B,S]
    const int*   __restrict__ labels,  // [B,S]
    int S)
{
    constexpr int L = 128;
    extern __shared__ char sm[];
    char*  ebuf0 = sm;
    char*  ebuf1 = sm + EBUF_BYTES;
    int*   smask = (int*)(sm + 2 * EBUF_BYTES);
    float* sred  = (float*)(sm + 2 * EBUF_BYTES + S * 4);

    const int tid = threadIdx.x;
    const int b   = blockIdx.x;
    const int col = tid >> 1;
    const int ih  = tid & 1;
    const int i0  = 64 * ih;

    const float* fb = feats + (size_t)b * S * L;

    // ---- expT slice into registers: 64 i-rows of this thread's column ----
    u64 TT[32];
    {
        const float* tr = trans + (size_t)i0 * L + col;
        #pragma unroll
        for (int k = 0; k < 32; ++k) {
            float t0 = __expf(__ldg(tr + (size_t)(2 * k) * L));
            float t1 = __expf(__ldg(tr + (size_t)(2 * k + 1) * L));
            TT[k] = pack2f(t0, t1);
        }
    }
    for (int k = tid; k < S; k += 256) smask[k] = mask[b * S + k];

    // ---- alpha0 (reduce over one value per column; pair threads duplicate) ----
    float a0 = startT[col] + fb[col];
    __syncthreads();                       // smask ready
    float m0 = ctamax(a0, sred, tid);
    float v = __expf(a0 - m0);             // exp-domain alpha, max-normalized
    float offset = m0;
    if (ih == 0) *(float*)(ebuf1 + (col >> 6) * EHALF_BYTES + (col & 63) * 4) = v;

    float fA = fb[L + col];                             // feat(t=1)
    float fB = (S > 2) ? fb[2 * (size_t)L + col] : 0.f; // feat(t=2)
    __syncthreads();

    char* rbuf = ebuf1;
    char* wbuf = ebuf0;
    const int myoff = (col >> 6) * EHALF_BYTES + (col & 63) * 4;

    for (int t = 1; t < S; ++t) {
        const ulonglong2* se = (const ulonglong2*)(rbuf + ih * EHALF_BYTES);
        u64 acc0 = 0ULL, acc1 = 0ULL, acc2 = 0ULL, acc3 = 0ULL;
        #pragma unroll
        for (int p = 0; p < 16; p += 2) {
            ulonglong2 eA = se[p];        // (e_{4p},e_{4p+1}),(e_{4p+2},e_{4p+3})
            ulonglong2 eB = se[p + 1];
            ffma2(acc0, eA.x, TT[2 * p]);
            ffma2(acc1, eA.y, TT[2 * p + 1]);
            ffma2(acc2, eB.x, TT[2 * p + 2]);
            ffma2(acc3, eB.y, TT[2 * p + 3]);
        }
        u64 accm = fadd2(fadd2(acc0, acc1), fadd2(acc2, acc3));
        float lo, hi; unpack2(accm, lo, hi);
        float sh = lo + hi;                              // my i-half's sum
        float s  = sh + __shfl_xor_sync(FULLMASK, sh, 1); // + other half

        float fcur = fA;
        fA = fB;
        if (t + 2 < S) fB = fb[(size_t)(t + 2) * L + col];   // prefetch

        if (smask[t]) v = s * __expf(fcur);
        // else masked: alpha (v) carries over unchanged

        if ((t & 7) == 0) {   // deferred rescale: keep exp-domain in fp32 range
            float mm = ctamax(v, sred, tid);
            v *= (1.0f / mm);
            offset += __logf(mm);
        }
        if (ih == 0) *(float*)(wbuf + myoff) = v;
        { char* tmp = rbuf; rbuf = wbuf; wbuf = tmp; }
        __syncthreads();
    }

    // ---- denominator ----
    float contrib = (ih == 0) ? v * __expf(endT[col]) : 0.f;
    float ssum = ctasum(contrib, sred, tid);
    float log_den = offset + __logf(ssum);

    // ---- numerator: label-path score ----
    float num = 0.f;
    float slf = 0.f;
    const int* lb = labels + b * S;
    for (int k = tid; k < S; k += 256) {
        int mk = smask[k];
        slf += (float)mk;
        int lab = lb[k]; if (lab == -100) lab = 0;
        if (k == 0) {
            num += startT[lab] + fb[lab];
        } else if (mk) {
            int lp = lb[k - 1]; if (lp == -100) lp = 0;
            num += trans[lp * L + lab] + fb[(size_t)k * L + lab];
        }
    }
    num = ctasum(num, sred, tid);
    slf = ctasum(slf, sred, tid);
    int lastt = (int)(slf + 0.5f) - 1;
    if (lastt < 0) lastt = 0;
    int lastlab = lb[lastt]; if (lastlab == -100) lastlab = 0;
    num += endT[lastlab];

    if (tid == 0) g_losses[b] = (log_den - num) * conf[b];
}

__global__ void k_finalize(float* __restrict__ out, int B) {
    int t = threadIdx.x;
    float x = (t < B) ? g_losses[t] : 0.f;
    #pragma unroll
    for (int o = 16; o; o >>= 1) x += __shfl_xor_sync(FULLMASK, x, o);
    __shared__ float sh[8];
    if ((t & 31) == 0) sh[t >> 5] = x;
    __syncthreads();
    if (t == 0) {
        float s = 0.f;
        int nw = (blockDim.x + 31) >> 5;
        for (int w = 0; w < nw; ++w) s += sh[w];
        out[0] = s / (float)B;
    }
}

extern "C" void kernel_launch(void* const* d_in, const int* in_sizes, int n_in,
                              void* d_out, int out_size) {
    const float* feats  = (const float*)d_in[0];
    const float* startT = (const float*)d_in[1];
    const float* endT   = (const float*)d_in[2];
    const float* trans  = (const float*)d_in[3];
    const float* conf   = (const float*)d_in[4];
    const int*   mask   = (const int*)  d_in[5];
    const int*   labels = (const int*)  d_in[6];

    const int B = in_sizes[4];            // 256
    const int S = in_sizes[5] / B;        // 512
    (void)n_in; (void)out_size;

    size_t smem = 2 * EBUF_BYTES          // double-buffered e vectors
                + (size_t)S * 4           // mask
                + 64;                     // reduction scratch (8 warps)

    k_crf_forward<<<B, 256, smem>>>(feats, startT, endT, trans, conf,
                                    mask, labels, S);
    k_finalize<<<1, 256>>>((float*)d_out, B);
}

// round 4
// speedup vs baseline: 2.4781x; 1.1292x over previous
#include <cuda_runtime.h>
#include <cuda_bf16.h>

#define FULLMASK 0xffffffffu

__device__ float g_losses[256];

// e-vector buffer (bf16): half0 = 64 bf16 @ byte 0 (128B), half1 @ byte 144.
// 144 = 128 + 16 pad so even-lane/odd-lane LDS.128 hit distinct banks.
#define EHALF_BYTES 144
#define EBUF_BYTES  (2 * EHALF_BYTES)

// CTA-wide reductions over 256 threads (8 warps).
__device__ __forceinline__ float ctamax(float v, volatile float* sred, int tid) {
    #pragma unroll
    for (int o = 16; o; o >>= 1) v = fmaxf(v, __shfl_xor_sync(FULLMASK, v, o));
    if ((tid & 31) == 0) sred[tid >> 5] = v;
    __syncthreads();
    v = fmaxf(fmaxf(fmaxf(sred[0], sred[1]), fmaxf(sred[2], sred[3])),
              fmaxf(fmaxf(sred[4], sred[5]), fmaxf(sred[6], sred[7])));
    __syncthreads();
    return v;
}
__device__ __forceinline__ float ctasum(float v, volatile float* sred, int tid) {
    #pragma unroll
    for (int o = 16; o; o >>= 1) v += __shfl_xor_sync(FULLMASK, v, o);
    if ((tid & 31) == 0) sred[tid >> 5] = v;
    __syncthreads();
    v = (sred[0] + sred[1]) + (sred[2] + sred[3])
      + (sred[4] + sred[5]) + (sred[6] + sred[7]);
    __syncthreads();
    return v;
}

// One CTA per batch element. 256 threads, 2 CTAs/SM.
// thread = (column, i-half): col = tid>>1, ih = tid&1 (i in [64*ih, 64*ih+64)).
// Matvec in bf16 (HFMA2 pipe, 2x fp32 FMA rate); everything else fp32-exact.
__global__ void __launch_bounds__(256, 2) k_crf_forward(
    const float* __restrict__ feats,   // [B,S,L]
    const float* __restrict__ startT,  // [L]
    const float* __restrict__ endT,    // [L]
    const float* __restrict__ trans,   // [L,L]
    const float* __restrict__ conf,    // [B]
    const int*   __restrict__ mask,    // [B,S]
    const int*   __restrict__ labels,  // [B,S]
    int S)
{
    constexpr int L = 128;
    extern __shared__ char sm[];
    char*  ebuf0 = sm;
    char*  ebuf1 = sm + EBUF_BYTES;
    int*   smask = (int*)(sm + 2 * EBUF_BYTES);
    float* sred  = (float*)(sm + 2 * EBUF_BYTES + S * 4);

    const int tid = threadIdx.x;
    const int b   = blockIdx.x;
    const int col = tid >> 1;
    const int ih  = tid & 1;
    const int i0  = 64 * ih;

    const float* fb = feats + (size_t)b * S * L;

    // ---- expT slice into bf16x2 registers: 64 i-rows of this column ----
    __nv_bfloat162 TT[32];
    {
        const float* tr = trans + (size_t)i0 * L + col;
        #pragma unroll
        for (int k = 0; k < 32; ++k) {
            float t0 = __expf(__ldg(tr + (size_t)(2 * k) * L));
            float t1 = __expf(__ldg(tr + (size_t)(2 * k + 1) * L));
            TT[k] = __floats2bfloat162_rn(t0, t1);
        }
    }
    for (int k = tid; k < S; k += 256) smask[k] = mask[b * S + k];

    // ---- alpha0 ----
    float a0 = startT[col] + fb[col];
    __syncthreads();                       // smask ready
    float m0 = ctamax(a0, sred, tid);
    float v = __expf(a0 - m0);             // exp-domain alpha, max-normalized
    float offset = m0;
    const int myoff = (col >> 6) * EHALF_BYTES + (col & 63) * 2;
    if (ih == 0) *(__nv_bfloat16*)(ebuf1 + myoff) = __float2bfloat16(v);

    float fA = fb[L + col];                             // feat(t=1)
    float fB = (S > 2) ? fb[2 * (size_t)L + col] : 0.f; // feat(t=2)
    __syncthreads();

    char* rbuf = ebuf1;
    char* wbuf = ebuf0;
    const __nv_bfloat162 bzero = __floats2bfloat162_rn(0.f, 0.f);

    for (int t = 1; t < S; ++t) {
        const uint4* se = (const uint4*)(rbuf + ih * EHALF_BYTES);
        __nv_bfloat162 acc0 = bzero, acc1 = bzero, acc2 = bzero, acc3 = bzero;
        __nv_bfloat162 acc4 = bzero, acc5 = bzero, acc6 = bzero, acc7 = bzero;
        #pragma unroll
        for (int p = 0; p < 8; p += 2) {
            uint4 qa = se[p];       // e[8p .. 8p+7]   as 4 bf16x2
            uint4 qb = se[p + 1];   // e[8p+8 .. 8p+15]
            acc0 = __hfma2(*(__nv_bfloat162*)&qa.x, TT[4 * p + 0], acc0);
            acc1 = __hfma2(*(__nv_bfloat162*)&qa.y, TT[4 * p + 1], acc1);
            acc2 = __hfma2(*(__nv_bfloat162*)&qa.z, TT[4 * p + 2], acc2);
            acc3 = __hfma2(*(__nv_bfloat162*)&qa.w, TT[4 * p + 3], acc3);
            acc4 = __hfma2(*(__nv_bfloat162*)&qb.x, TT[4 * p + 4], acc4);
            acc5 = __hfma2(*(__nv_bfloat162*)&qb.y, TT[4 * p + 5], acc5);
            acc6 = __hfma2(*(__nv_bfloat162*)&qb.z, TT[4 * p + 6], acc6);
            acc7 = __hfma2(*(__nv_bfloat162*)&qb.w, TT[4 * p + 7], acc7);
        }
        // tree-combine 8 bf16x2 chains, then to fp32
        acc0 = __hadd2(acc0, acc1);
        acc2 = __hadd2(acc2, acc3);
        acc4 = __hadd2(acc4, acc5);
        acc6 = __hadd2(acc6, acc7);
        acc0 = __hadd2(acc0, acc2);
        acc4 = __hadd2(acc4, acc6);
        float sh = __low2float(acc0) + __high2float(acc0)
                 + __low2float(acc4) + __high2float(acc4);
        float s  = sh + __shfl_xor_sync(FULLMASK, sh, 1); // + other i-half

        float fcur = fA;
        fA = fB;
        if (t + 2 < S) fB = fb[(size_t)(t + 2) * L + col];   // prefetch

        if (smask[t]) v = s * __expf(fcur);
        // else masked: alpha (v) carries over unchanged

        if ((t & 7) == 0) {   // deferred rescale: keep exp-domain in range
            float mm = ctamax(v, sred, tid);
            v *= (1.0f / mm);
            offset += __logf(mm);
        }
        if (ih == 0) *(__nv_bfloat16*)(wbuf + myoff) = __float2bfloat16(v);
        { char* tmp = rbuf; rbuf = wbuf; wbuf = tmp; }
        __syncthreads();
    }

    // ---- denominator (fp32 exact on final v) ----
    float contrib = (ih == 0) ? v * __expf(endT[col]) : 0.f;
    float ssum = ctasum(contrib, sred, tid);
    float log_den = offset + __logf(ssum);

    // ---- numerator: label-path score (exact fp32) ----
    float num = 0.f;
    float slf = 0.f;
    const int* lb = labels + b * S;
    for (int k = tid; k < S; k += 256) {
        int mk = smask[k];
        slf += (float)mk;
        int lab = lb[k]; if (lab == -100) lab = 0;
        if (k == 0) {
            num += startT[lab] + fb[lab];
        } else if (mk) {
            int lp = lb[k - 1]; if (lp == -100) lp = 0;
            num += trans[lp * L + lab] + fb[(size_t)k * L + lab];
        }
    }
    num = ctasum(num, sred, tid);
    slf = ctasum(slf, sred, tid);
    int lastt = (int)(slf + 0.5f) - 1;
    if (lastt < 0) lastt = 0;
    int lastlab = lb[lastt]; if (lastlab == -100) lastlab = 0;
    num += endT[lastlab];

    if (tid == 0) g_losses[b] = (log_den - num) * conf[b];
}

__global__ void k_finalize(float* __restrict__ out, int B) {
    int t = threadIdx.x;
    float x = (t < B) ? g_losses[t] : 0.f;
    #pragma unroll
    for (int o = 16; o; o >>= 1) x += __shfl_xor_sync(FULLMASK, x, o);
    __shared__ float sh[8];
    if ((t & 31) == 0) sh[t >> 5] = x;
    __syncthreads();
    if (t == 0) {
        float s = 0.f;
        int nw = (blockDim.x + 31) >> 5;
        for (int w = 0; w < nw; ++w) s += sh[w];
        out[0] = s / (float)B;
    }
}

extern "C" void kernel_launch(void* const* d_in, const int* in_sizes, int n_in,
                              void* d_out, int out_size) {
    const float* feats  = (const float*)d_in[0];
    const float* startT = (const float*)d_in[1];
    const float* endT   = (const float*)d_in[2];
    const float* trans  = (const float*)d_in[3];
    const float* conf   = (const float*)d_in[4];
    const int*   mask   = (const int*)  d_in[5];
    const int*   labels = (const int*)  d_in[6];

    const int B = in_sizes[4];            // 256
    const int S = in_sizes[5] / B;        // 512
    (void)n_in; (void)out_size;

    size_t smem = 2 * EBUF_BYTES          // double-buffered bf16 e vectors
                + (size_t)S * 4           // mask
                + 64;                     // reduction scratch (8 warps)

    k_crf_forward<<<B, 256, smem>>>(feats, startT, endT, trans, conf,
                                    mask, labels, S);
    k_finalize<<<1, 256>>>((float*)d_out, B);
}

// round 5
// speedup vs baseline: 3.4599x; 1.3962x over previous
#include <cuda_runtime.h>
#include <cuda_bf16.h>

#define FULLMASK 0xffffffffu

__device__ float g_losses[256];

// Reductions over 64 threads (2 warps).
__device__ __forceinline__ float ctamax64(float v, volatile float* sred, int tid) {
    #pragma unroll
    for (int o = 16; o; o >>= 1) v = fmaxf(v, __shfl_xor_sync(FULLMASK, v, o));
    if ((tid & 31) == 0) sred[tid >> 5] = v;
    __syncthreads();
    v = fmaxf(sred[0], sred[1]);
    __syncthreads();
    return v;
}
__device__ __forceinline__ float ctasum64(float v, volatile float* sred, int tid) {
    #pragma unroll
    for (int o = 16; o; o >>= 1) v += __shfl_xor_sync(FULLMASK, v, o);
    if ((tid & 31) == 0) sred[tid >> 5] = v;
    __syncthreads();
    v = sred[0] + sred[1];
    __syncthreads();
    return v;
}

// One CTA per batch element. 64 threads; thread owns columns (2*tid, 2*tid+1)
// over the FULL i-range. expT in registers (128 bf16x2). One barrier per step,
// no shuffles in the hot loop, rescale piggybacks on e[0] (no extra barriers).
__global__ void __launch_bounds__(64, 2) k_crf_forward(
    const float* __restrict__ feats,   // [B,S,L]
    const float* __restrict__ startT,  // [L]
    const float* __restrict__ endT,    // [L]
    const float* __restrict__ trans,   // [L,L]
    const float* __restrict__ conf,    // [B]
    const int*   __restrict__ mask,    // [B,S]
    const int*   __restrict__ labels,  // [B,S]
    int S)
{
    constexpr int L = 128;
    extern __shared__ char sm[];
    unsigned* eb0  = (unsigned*)sm;               // 64 x bf16x2 = 256B
    unsigned* eb1  = (unsigned*)(sm + 256);       // 256B
    int*      smask = (int*)(sm + 512);           // S ints
    float*    sred  = (float*)(sm + 512 + S * 4); // 2 floats

    const int tid = threadIdx.x;
    const int b   = blockIdx.x;
    const int c0  = 2 * tid;
    const int c1  = 2 * tid + 1;

    const float*  fb  = feats + (size_t)b * S * L;
    const float2* fb2 = (const float2*)fb;        // [S][64] float2 view

    // ---- expT slices into registers: 64 bf16x2 per column ----
    __nv_bfloat162 T0[64], T1[64];
    #pragma unroll
    for (int k = 0; k < 64; ++k) {
        const float* r0 = trans + (size_t)(2 * k) * L;
        const float* r1 = trans + (size_t)(2 * k + 1) * L;
        T0[k] = __floats2bfloat162_rn(__expf(__ldg(r0 + c0)), __expf(__ldg(r1 + c0)));
        T1[k] = __floats2bfloat162_rn(__expf(__ldg(r0 + c1)), __expf(__ldg(r1 + c1)));
    }
    for (int k = tid; k < S; k += 64) smask[k] = mask[b * S + k];

    // ---- alpha0 ----
    float a00 = startT[c0] + fb[c0];
    float a01 = startT[c1] + fb[c1];
    __syncthreads();                       // smask ready
    float m0 = ctamax64(fmaxf(a00, a01), sred, tid);
    float v0 = __expf(a00 - m0);
    float v1 = __expf(a01 - m0);
    float offset = m0;                     // alpha = offset + log(v)
    eb1[tid] = *(unsigned*)&(__nv_bfloat162&)*(__nv_bfloat162*)&(
        (__nv_bfloat162&)*(__nv_bfloat162[1]){__floats2bfloat162_rn(v0, v1)});
    // (simple form:)
    { __nv_bfloat162 pk = __floats2bfloat162_rn(v0, v1); eb1[tid] = *(unsigned*)&pk; }

    float2 fA = fb2[64 + tid];                               // feat(t=1)
    float2 fB = (S > 2) ? fb2[2 * 64 + tid] : make_float2(0.f, 0.f);
    __syncthreads();

    const __nv_bfloat162 bz = __floats2bfloat162_rn(0.f, 0.f);

    for (int t = 1; t < S; ++t) {
        const uint4* se = (const uint4*)((t & 1) ? eb1 : eb0);  // read buffer
        unsigned*    wb = (t & 1) ? eb0 : eb1;                  // write buffer

        __nv_bfloat162 a0 = bz, a1 = bz, a2 = bz, a3 = bz;      // col c0 chains
        __nv_bfloat162 b0 = bz, b1 = bz, b2 = bz, b3 = bz;      // col c1 chains
        float e0f = 1.0f;
        #pragma unroll
        for (int p = 0; p < 16; ++p) {
            uint4 q = se[p];                      // e[8p .. 8p+7]
            __nv_bfloat162 q0 = *(__nv_bfloat162*)&q.x;
            __nv_bfloat162 q1 = *(__nv_bfloat162*)&q.y;
            __nv_bfloat162 q2 = *(__nv_bfloat162*)&q.z;
            __nv_bfloat162 q3 = *(__nv_bfloat162*)&q.w;
            if (p == 0) e0f = __low2float(q0);    // e[0]: free normalizer
            a0 = __hfma2(q0, T0[4 * p + 0], a0);
            a1 = __hfma2(q1, T0[4 * p + 1], a1);
            a2 = __hfma2(q2, T0[4 * p + 2], a2);
            a3 = __hfma2(q3, T0[4 * p + 3], a3);
            b0 = __hfma2(q0, T1[4 * p + 0], b0);
            b1 = __hfma2(q1, T1[4 * p + 1], b1);
            b2 = __hfma2(q2, T1[4 * p + 2], b2);
            b3 = __hfma2(q3, T1[4 * p + 3], b3);
        }
        a0 = __hadd2(a0, a1); a2 = __hadd2(a2, a3); a0 = __hadd2(a0, a2);
        b0 = __hadd2(b0, b1); b2 = __hadd2(b2, b3); b0 = __hadd2(b0, b2);
        float s0 = __low2float(a0) + __high2float(a0);
        float s1 = __low2float(b0) + __high2float(b0);

        float2 fcur = fA;
        fA = fB;
        if (t + 2 < S) fB = fb2[(size_t)(t + 2) * 64 + tid];   // prefetch

        if (smask[t]) {
            v0 = s0 * __expf(fcur.x);
            v1 = s1 * __expf(fcur.y);
            if ((t & 3) == 0) {   // uniform rescale by e[0] (exact accounting)
                float r = __frcp_rn(e0f);
                v0 *= r; v1 *= r;
                offset += __logf(e0f);
            }
        }
        // else masked: alpha (v0,v1) carries over unchanged

        __nv_bfloat162 pk = __floats2bfloat162_rn(v0, v1);
        wb[tid] = *(unsigned*)&pk;
        __syncthreads();
    }

    // ---- denominator ----
    float contrib = v0 * __expf(endT[c0]) + v1 * __expf(endT[c1]);
    float ssum = ctasum64(contrib, sred, tid);
    float log_den = offset + __logf(ssum);

    // ---- numerator: label-path score (exact fp32) ----
    float num = 0.f;
    float slf = 0.f;
    const int* lb = labels + b * S;
    for (int k = tid; k < S; k += 64) {
        int mk = smask[k];
        slf += (float)mk;
        int lab = lb[k]; if (lab == -100) lab = 0;
        if (k == 0) {
            num += startT[lab] + fb[lab];
        } else if (mk) {
            int lp = lb[k - 1]; if (lp == -100) lp = 0;
            num += trans[lp * L + lab] + fb[(size_t)k * L + lab];
        }
    }
    num = ctasum64(num, sred, tid);
    slf = ctasum64(slf, sred, tid);
    int lastt = (int)(slf + 0.5f) - 1;
    if (lastt < 0) lastt = 0;
    int lastlab = lb[lastt]; if (lastlab == -100) lastlab = 0;
    num += endT[lastlab];

    if (tid == 0) g_losses[b] = (log_den - num) * conf[b];
}

__global__ void k_finalize(float* __restrict__ out, int B) {
    int t = threadIdx.x;
    float x = (t < B) ? g_losses[t] : 0.f;
    #pragma unroll
    for (int o = 16; o; o >>= 1) x += __shfl_xor_sync(FULLMASK, x, o);
    __shared__ float sh[8];
    if ((t & 31) == 0) sh[t >> 5] = x;
    __syncthreads();
    if (t == 0) {
        float s = 0.f;
        int nw = (blockDim.x + 31) >> 5;
        for (int w = 0; w < nw; ++w) s += sh[w];
        out[0] = s / (float)B;
    }
}

extern "C" void kernel_launch(void* const* d_in, const int* in_sizes, int n_in,
                              void* d_out, int out_size) {
    const float* feats  = (const float*)d_in[0];
    const float* startT = (const float*)d_in[1];
    const float* endT   = (const float*)d_in[2];
    const float* trans  = (const float*)d_in[3];
    const float* conf   = (const float*)d_in[4];
    const int*   mask   = (const int*)  d_in[5];
    const int*   labels = (const int*)  d_in[6];

    const int B = in_sizes[4];            // 256
    const int S = in_sizes[5] / B;        // 512
    (void)n_in; (void)out_size;

    size_t smem = 512                     // double-buffered bf16 e vectors
                + (size_t)S * 4           // mask
                + 16;                     // reduction scratch

    k_crf_forward<<<B, 64, smem>>>(feats, startT, endT, trans, conf,
                                   mask, labels, S);
    k_finalize<<<1, 256>>>((float*)d_out, B);
}